// round 13
// baseline (speedup 1.0000x reference)
#include <cuda_runtime.h>
#include <stdint.h>

// ROISelect: per-row top-k(score) + ROI gather, SINGLE fused kernel.
// Grid (2,128): each CTA scans half a row (16 float4/thread, 2 CTAs/SM =>
// 64 warps/SM), filters score >= 2.80 (~168 cand/half, 4.3-sigma margin)
// into an smem stage, flushes to global scratch with one atomic. The LAST
// CTA to finish a row (per-row arrival counter + threadfence) becomes the
// finisher: it loads both halves' candidates and computes exact sorted
// ranks (2 threads per candidate over unique u64 keys value|~index,
// tf.nn.top_k tie order), emitting out[rank] + gathered ROI. Finisher work
// overlaps other rows' scans. Exact 12-bit radix-select fallback if count
// is outside [256, 4096].
//
// SMEM: one 36 KB dynamic arena (< 48 KB, no opt-in attribute needed):
//   cand[CAP]  32 KB   (finisher candidate buffer / fallback hist+sdata)
//   s_half      4 KB   (split-rank partials)
//   stage      16 KB   aliases cand[0..SCAP) — dead before finisher writes.

#define B_ROWS 128
#define N_COLS 131072
#define K_TOP  256
#define CAP    4096

#define TPB        1024
#define HALVES     2
#define HALF_ELEMS (N_COLS / HALVES)          // 65536
#define A_V4       (HALF_ELEMS / 4 / TPB)     // 16 float4 per thread
#define A_GROUPS   4
#define A_GSIZE    (A_V4 / A_GROUPS)          // 4 float4 per load group
#define SCAP       2048                       // smem stage (16 KB, aliases cand)
#define VEC_ITERS  (N_COLS / 4 / TPB)         // 32 (fallback only)

#define DYN_SMEM_BYTES (CAP * 8 + TPB * 4)    // 36864 < 49152

__device__ unsigned long long g_cand[B_ROWS * CAP];
__device__ unsigned int       g_cnt[B_ROWS];    // zero at load; finisher resets
__device__ unsigned int       g_done[B_ROWS];   // zero at load; finisher resets

__device__ __forceinline__ unsigned int f2u(float f) {
    unsigned int b = __float_as_uint(f);
    return (b & 0x80000000u) ? ~b : (b | 0x80000000u);
}
__device__ __forceinline__ float u2f(unsigned int u) {
    unsigned int b = (u & 0x80000000u) ? (u ^ 0x80000000u) : ~u;
    return __uint_as_float(b);
}

__global__ __launch_bounds__(TPB, 2)
void roiselect_fused_kernel(const float* __restrict__ score,
                            const float* __restrict__ roi,
                            float* __restrict__ out_roi,
                            float* __restrict__ out_score)
{
    __shared__ int s_cnt;
    __shared__ int s_bin;
    __shared__ unsigned int s_base;
    __shared__ unsigned int s_fin;
    __shared__ unsigned int s_count;
    extern __shared__ unsigned long long dyn[];
    unsigned long long* cand   = dyn;                         // CAP entries
    unsigned int*       s_half = (unsigned int*)(dyn + CAP);  // TPB entries
    unsigned long long* stage  = dyn;                         // aliases cand[0..SCAP)

    const int tid  = threadIdx.x;
    const int half = blockIdx.x;
    const int row  = blockIdx.y;

    if (tid == 0) s_cnt = 0;
    __syncthreads();

    // ================= Scan: filter half a row into smem stage =================
    const float4* sc4 =
        (const float4*)(score + (size_t)row * N_COLS + (size_t)half * HALF_ELEMS);
    const int gbase = half * HALF_ELEMS;
    const float TGUESS = 2.80f;

    #pragma unroll
    for (int g = 0; g < A_GROUPS; ++g) {
        float4 v[A_GSIZE];
        #pragma unroll
        for (int u = 0; u < A_GSIZE; ++u)
            v[u] = sc4[tid + (g * A_GSIZE + u) * TPB];
        #pragma unroll
        for (int u = 0; u < A_GSIZE; ++u) {
            int ebase = gbase + (tid + (g * A_GSIZE + u) * TPB) * 4;
            float vals[4] = {v[u].x, v[u].y, v[u].z, v[u].w};
            #pragma unroll
            for (int c = 0; c < 4; ++c) {
                if (vals[c] >= TGUESS) {
                    int pos = atomicAdd(&s_cnt, 1);
                    if (pos < SCAP) {
                        unsigned int uu = __float_as_uint(vals[c]) | 0x80000000u;
                        stage[pos] = ((unsigned long long)uu << 32)
                                   | (unsigned int)~(unsigned int)(ebase + c);
                    }
                }
            }
        }
    }
    __syncthreads();

    // ================= Flush stage -> global scratch =================
    {
        int raw = s_cnt;
        int cnt = min(raw, SCAP);
        if (tid == 0) {
            unsigned int add = (unsigned int)raw;
            if (raw > SCAP) add += (1u << 20);   // flag overflow -> fallback
            s_base = atomicAdd(&g_cnt[row], add);
        }
        __syncthreads();
        unsigned int base = s_base;
        unsigned long long* dst = g_cand + (size_t)row * CAP;
        for (int i = tid; i < cnt; i += TPB) {
            unsigned int p = base + (unsigned int)i;
            if (p < CAP) dst[p] = stage[i];
        }
    }

    // ================= Last-CTA-per-row election =================
    __syncthreads();
    __threadfence();                 // order g_cand/g_cnt writes before g_done
    if (tid == 0) {
        unsigned int old = atomicAdd(&g_done[row], 1u);
        unsigned int fin = (old == HALVES - 1) ? 1u : 0u;
        if (fin) {
            __threadfence();         // acquire: see peer CTA's g_cand writes
            s_count = g_cnt[row];
            g_cnt[row]  = 0;         // reset for next graph replay
            g_done[row] = 0;
        }
        s_fin = fin;
    }
    __syncthreads();
    if (!s_fin) return;              // non-finisher CTA exits

    // ================= Finisher: load candidates =================
    unsigned int count = s_count;
    const unsigned long long* src = g_cand + (size_t)row * CAP;

    if (count >= K_TOP && count <= CAP) {
        for (unsigned int i = tid; i < count; i += TPB)
            cand[i] = src[i];
    } else {
        // ---------- Exact fallback: 12-bit radix select over the raw row ----------
        const float4* fr4 = (const float4*)(score + (size_t)row * N_COLS);
        unsigned int* hist  = (unsigned int*)cand;   // 4096 bins (aliased)
        unsigned int* sdata = hist + 4096;           // 1024 thread sums
        for (int i = tid; i < 4096; i += TPB) hist[i] = 0;
        if (tid == 0) s_cnt = 0;
        __syncthreads();

        for (int i = 0; i < VEC_ITERS; ++i) {
            float4 f = fr4[tid + i * TPB];
            float vals[4] = {f.x, f.y, f.z, f.w};
            #pragma unroll
            for (int c = 0; c < 4; ++c)
                atomicAdd(&hist[f2u(vals[c]) >> 20], 1u);
        }
        __syncthreads();

        unsigned int h0 = hist[4*tid+0], h1 = hist[4*tid+1];
        unsigned int h2 = hist[4*tid+2], h3 = hist[4*tid+3];
        sdata[tid] = h0 + h1 + h2 + h3;
        __syncthreads();
        for (int d = 1; d < TPB; d <<= 1) {          // inclusive suffix scan
            unsigned int vv = (tid + d < TPB) ? sdata[tid + d] : 0u;
            __syncthreads();
            sdata[tid] += vv;
            __syncthreads();
        }
        unsigned int Anext = (tid + 1 < TPB) ? sdata[tid + 1] : 0u;
        unsigned int cum3 = Anext + h3;
        unsigned int cum2 = cum3 + h2;
        unsigned int cum1 = cum2 + h1;
        unsigned int cum0 = cum1 + h0;
        if (cum3 >= K_TOP && Anext < K_TOP) s_bin = 4*tid + 3;
        if (cum2 >= K_TOP && cum3  < K_TOP) s_bin = 4*tid + 2;
        if (cum1 >= K_TOP && cum2  < K_TOP) s_bin = 4*tid + 1;
        if (cum0 >= K_TOP && cum1  < K_TOP) s_bin = 4*tid + 0;
        __syncthreads();
        unsigned int uthr = (unsigned int)s_bin << 20;
        __syncthreads();   // uthr read by all; hist region can be overwritten

        for (int i = 0; i < VEC_ITERS; ++i) {
            int v4i = tid + i * TPB;
            float4 f = fr4[v4i];
            int ebase = v4i * 4;
            float vals[4] = {f.x, f.y, f.z, f.w};
            #pragma unroll
            for (int c = 0; c < 4; ++c) {
                unsigned int u = f2u(vals[c]);
                if (u >= uthr) {
                    int pos = atomicAdd(&s_cnt, 1);
                    if (pos < CAP)
                        cand[pos] = ((unsigned long long)u << 32)
                                  | (unsigned int)~(unsigned int)(ebase + c);
                }
            }
        }
        __syncthreads();
        count = min((unsigned int)s_cnt, (unsigned int)CAP);
    }

    // Pad to even (a 0 key never outranks a real key: bit 63 set on real keys).
    if (tid == 0 && (count & 1u)) cand[count] = 0ULL;
    __syncthreads();
    const int pairs = (int)((count + 1u) >> 1);
    const ulonglong2* c2 = (const ulonglong2*)cand;

    if (count <= 512) {
        // ---------- Split rank: 2 threads per candidate ----------
        const int t     = tid & 511;
        const int which = tid >> 9;
        const int ph    = pairs >> 1;
        const int i0    = which ? ph : 0;
        const int i1    = which ? pairs : ph;
        unsigned int partial = 0;
        if (t < (int)count) {
            const unsigned long long key = cand[t];
            #pragma unroll 4
            for (int i = i0; i < i1; ++i) {
                ulonglong2 p = c2[i];
                partial += (p.x > key) + (p.y > key);
            }
        }
        s_half[tid] = partial;
        __syncthreads();

        if (tid < (int)count) {
            unsigned int rank = s_half[tid] + s_half[tid + 512];
            if (rank < K_TOP) {
                unsigned long long key = cand[tid];
                unsigned int u   = (unsigned int)(key >> 32);
                unsigned int idx = ~(unsigned int)key;
                const float4* r4 = (const float4*)roi;
                float4 rv = r4[(size_t)row * N_COLS + idx];
                out_score[row * K_TOP + rank] = u2f(u);
                ((float4*)out_roi)[row * K_TOP + rank] = rv;
            }
        }
    } else {
        // ---------- Serial rank (fallback-sized candidate sets only) ----------
        for (int c = tid; c < (int)count; c += TPB) {
            unsigned long long key = cand[c];
            int rank = 0;
            #pragma unroll 8
            for (int i = 0; i < pairs; ++i) {
                ulonglong2 p = c2[i];
                rank += (p.x > key) + (p.y > key);
            }
            if (rank < K_TOP) {
                unsigned int u   = (unsigned int)(key >> 32);
                unsigned int idx = ~(unsigned int)key;
                const float4* r4 = (const float4*)roi;
                float4 rv = r4[(size_t)row * N_COLS + idx];
                out_score[row * K_TOP + rank] = u2f(u);
                ((float4*)out_roi)[row * K_TOP + rank] = rv;
            }
        }
    }
}

extern "C" void kernel_launch(void* const* d_in, const int* in_sizes, int n_in,
                              void* d_out, int out_size) {
    (void)in_sizes; (void)n_in; (void)out_size;
    const float* score = (const float*)d_in[0];
    const float* roi   = (const float*)d_in[1];
    float* out_roi   = (float*)d_out;                               // [128,256,4]
    float* out_score = (float*)d_out + (size_t)B_ROWS * K_TOP * 4;  // [128,256]

    dim3 grid(HALVES, B_ROWS);
    roiselect_fused_kernel<<<grid, TPB, DYN_SMEM_BYTES>>>(
        score, roi, out_roi, out_score);
}